// round 1
// baseline (speedup 1.0000x reference)
#include <cuda_runtime.h>
#include <math.h>

#define NTOK   49
#define CDIM   256
#define HEADS  8
#define HD     32
#define BMAX   2048
#define NN2    2401   // 49*49

// Scratch (allocation-free: __device__ globals)
__device__ float g_qkv[BMAX * 3 * HEADS * NTOK * HD];   // [B][3][H][49][32]  ~308MB
__device__ float g_att[BMAX * NTOK * CDIM];             // [B*49][256]        ~103MB
__device__ float g_bias[HEADS * NN2];                   // 16*sigmoid(cpb)    [h][i][j]

// ---------------------------------------------------------------------------
// CPB MLP: table[169,2] -> relu(@w1^T+b1)[169,512] -> @w2^T -> [169,8]
// then gather via rel_pos_index and apply 16*sigmoid. One tiny block.
// ---------------------------------------------------------------------------
__global__ void cpb_kernel(const float* __restrict__ table,   // 169*2
                           const float* __restrict__ w1,      // 512*2
                           const float* __restrict__ b1,      // 512
                           const float* __restrict__ w2,      // 8*512
                           const int*   __restrict__ idx)     // 2401
{
    __shared__ float t8[169][8];
    const int tid = threadIdx.x;
    for (int e = tid; e < 169 * 8; e += blockDim.x) {
        const int r = e >> 3, hh = e & 7;
        const float t0 = table[r * 2 + 0];
        const float t1 = table[r * 2 + 1];
        float s = 0.f;
        for (int j = 0; j < 512; ++j) {
            float hv = fmaf(t0, w1[j * 2 + 0], fmaf(t1, w1[j * 2 + 1], b1[j]));
            hv = fmaxf(hv, 0.f);
            s = fmaf(hv, w2[hh * 512 + j], s);
        }
        t8[r][hh] = s;
    }
    __syncthreads();
    for (int e = tid; e < HEADS * NN2; e += blockDim.x) {
        const int h = e / NN2, ij = e % NN2;
        const float bv = t8[idx[ij]][h];
        g_bias[e] = 16.f / (1.f + __expf(-bv));
    }
}

// ---------------------------------------------------------------------------
// SGEMM: Y[M,768] = X[M,256] @ W^T + qkv_bias, scattered into g_qkv layout
// BM=128, BN=64, BK=16, 256 threads, 8x4 per thread.
// ---------------------------------------------------------------------------
__global__ __launch_bounds__(256) void sgemm_qkv(const float* __restrict__ X,
                                                 const float* __restrict__ W,
                                                 const float* __restrict__ qb,
                                                 const float* __restrict__ vb)
{
    __shared__ float As[16][132];   // [k][m], 128 rows + pad
    __shared__ float Bs[16][68];    // [k][n], 64 cols + pad

    const int tid = threadIdx.x;
    const int tx = tid & 15;        // col group (4 cols)
    const int ty = tid >> 4;        // row group (8 rows)
    const int m0 = blockIdx.y * 128;
    const int n0 = blockIdx.x * 64;
    const int lr = tid >> 2;        // 0..63
    const int lc = (tid & 3) << 2;  // 0,4,8,12

    float acc[8][4];
#pragma unroll
    for (int i = 0; i < 8; ++i)
#pragma unroll
        for (int j = 0; j < 4; ++j) acc[i][j] = 0.f;

    for (int k0 = 0; k0 < 256; k0 += 16) {
        const float4 a0 = *(const float4*)&X[(size_t)(m0 + lr) * 256 + k0 + lc];
        const float4 a1 = *(const float4*)&X[(size_t)(m0 + lr + 64) * 256 + k0 + lc];
        const float4 b0 = *(const float4*)&W[(size_t)(n0 + lr) * 256 + k0 + lc];
        __syncthreads();
        As[lc + 0][lr] = a0.x; As[lc + 1][lr] = a0.y; As[lc + 2][lr] = a0.z; As[lc + 3][lr] = a0.w;
        As[lc + 0][lr + 64] = a1.x; As[lc + 1][lr + 64] = a1.y; As[lc + 2][lr + 64] = a1.z; As[lc + 3][lr + 64] = a1.w;
        Bs[lc + 0][lr] = b0.x; Bs[lc + 1][lr] = b0.y; Bs[lc + 2][lr] = b0.z; Bs[lc + 3][lr] = b0.w;
        __syncthreads();
#pragma unroll
        for (int kk = 0; kk < 16; ++kk) {
            const float4 av0 = *(const float4*)&As[kk][ty * 8];
            const float4 av1 = *(const float4*)&As[kk][ty * 8 + 4];
            const float4 bv  = *(const float4*)&Bs[kk][tx * 4];
            const float ar[8] = {av0.x, av0.y, av0.z, av0.w, av1.x, av1.y, av1.z, av1.w};
            const float br[4] = {bv.x, bv.y, bv.z, bv.w};
#pragma unroll
            for (int i = 0; i < 8; ++i)
#pragma unroll
                for (int j = 0; j < 4; ++j)
                    acc[i][j] = fmaf(ar[i], br[j], acc[i][j]);
        }
    }

    // scatter epilogue: col o -> (which, h, d); row m -> (b, n)
    const int which = n0 >> 8;          // uniform per block (n0 multiple of 64)
#pragma unroll
    for (int i = 0; i < 8; ++i) {
        const int m = m0 + ty * 8 + i;
        const int bb = m / NTOK, nn = m % NTOK;
#pragma unroll
        for (int j = 0; j < 4; ++j) {
            const int o = n0 + tx * 4 + j;
            const int rem = o & 255;
            const float bias = (which == 0) ? qb[rem] : ((which == 2) ? vb[rem] : 0.f);
            const int h = rem >> 5, d = rem & 31;
            g_qkv[((size_t)((bb * 3 + which) * HEADS + h)) * (NTOK * HD) + nn * HD + d] =
                acc[i][j] + bias;
        }
    }
}

// ---------------------------------------------------------------------------
// Attention: one block per (b, h). 128 threads (4 warps), lane == head-dim.
// ---------------------------------------------------------------------------
__global__ __launch_bounds__(128) void attn_kernel(const float* __restrict__ mask,
                                                   const float* __restrict__ logit_scale,
                                                   int nW)
{
    __shared__ float qn[NTOK][33];
    __shared__ float kn[NTOK][33];
    __shared__ float vs[NTOK][33];
    __shared__ float at[NTOK][56];

    const int b = blockIdx.x, h = blockIdx.y;
    const int tid = threadIdx.x, w = tid >> 5, lane = tid & 31;
    const float scale = __expf(fminf(logit_scale[h], 4.605170185988092f)); // ln(100)

    const float* qptr = &g_qkv[((size_t)((b * 3 + 0) * HEADS + h)) * (NTOK * HD)];
    const float* kptr = &g_qkv[((size_t)((b * 3 + 1) * HEADS + h)) * (NTOK * HD)];
    const float* vptr = &g_qkv[((size_t)((b * 3 + 2) * HEADS + h)) * (NTOK * HD)];

    // load + L2 normalize (fold logit scale into q)
    for (int r = w; r < NTOK; r += 4) {
        const float qv = qptr[r * HD + lane];
        const float kv = kptr[r * HD + lane];
        float sq = qv * qv, sk = kv * kv;
#pragma unroll
        for (int o = 16; o > 0; o >>= 1) {
            sq += __shfl_xor_sync(0xffffffffu, sq, o);
            sk += __shfl_xor_sync(0xffffffffu, sk, o);
        }
        qn[r][lane] = qv * (scale / fmaxf(sqrtf(sq), 1e-12f));
        kn[r][lane] = kv / fmaxf(sqrtf(sk), 1e-12f);
        vs[r][lane] = vptr[r * HD + lane];
    }
    __syncthreads();

    const int j2 = lane + 32;
    const int j2c = (j2 < NTOK) ? j2 : NTOK - 1;
    const float* bptr = &g_bias[h * NN2];
    const float* mptr = &mask[(size_t)(b % nW) * NN2];

    // QK^T + bias + mask
    for (int r = w; r < NTOK; r += 4) {
        float a0 = 0.f, a1 = 0.f;
#pragma unroll
        for (int d = 0; d < HD; ++d) {
            const float qd = qn[r][d];
            a0 = fmaf(qd, kn[lane][d], a0);
            a1 = fmaf(qd, kn[j2c][d], a1);
        }
        at[r][lane] = a0 + bptr[r * NTOK + lane] + mptr[r * NTOK + lane];
        if (j2 < NTOK) at[r][j2] = a1 + bptr[r * NTOK + j2] + mptr[r * NTOK + j2];
    }
    __syncthreads();

    // row softmax
    for (int r = w; r < NTOK; r += 4) {
        const float a0 = at[r][lane];
        const float a1 = (j2 < NTOK) ? at[r][j2] : -1e30f;
        float mx = fmaxf(a0, a1);
#pragma unroll
        for (int o = 16; o > 0; o >>= 1) mx = fmaxf(mx, __shfl_xor_sync(0xffffffffu, mx, o));
        const float e0 = __expf(a0 - mx);
        const float e1 = (j2 < NTOK) ? __expf(a1 - mx) : 0.f;
        float s = e0 + e1;
#pragma unroll
        for (int o = 16; o > 0; o >>= 1) s += __shfl_xor_sync(0xffffffffu, s, o);
        const float inv = 1.f / s;
        at[r][lane] = e0 * inv;
        if (j2 < NTOK) at[r][j2] = e1 * inv;
    }
    __syncthreads();

    // attn @ V -> g_att[b*49+r][h*32+lane]
    for (int r = w; r < NTOK; r += 4) {
        float acc = 0.f;
#pragma unroll
        for (int j = 0; j < NTOK; ++j) acc = fmaf(at[r][j], vs[j][lane], acc);
        g_att[((size_t)(b * NTOK + r)) * CDIM + h * HD + lane] = acc;
    }
}

// ---------------------------------------------------------------------------
// Proj SGEMM: out[M,256] = g_att[M,256] @ proj_w^T + proj_b
// ---------------------------------------------------------------------------
__global__ __launch_bounds__(256) void sgemm_proj(const float* __restrict__ W,
                                                  const float* __restrict__ pb,
                                                  float* __restrict__ out)
{
    __shared__ float As[16][132];
    __shared__ float Bs[16][68];

    const int tid = threadIdx.x;
    const int tx = tid & 15;
    const int ty = tid >> 4;
    const int m0 = blockIdx.y * 128;
    const int n0 = blockIdx.x * 64;
    const int lr = tid >> 2;
    const int lc = (tid & 3) << 2;

    float acc[8][4];
#pragma unroll
    for (int i = 0; i < 8; ++i)
#pragma unroll
        for (int j = 0; j < 4; ++j) acc[i][j] = 0.f;

    const float* X = g_att;
    for (int k0 = 0; k0 < 256; k0 += 16) {
        const float4 a0 = *(const float4*)&X[(size_t)(m0 + lr) * 256 + k0 + lc];
        const float4 a1 = *(const float4*)&X[(size_t)(m0 + lr + 64) * 256 + k0 + lc];
        const float4 b0 = *(const float4*)&W[(size_t)(n0 + lr) * 256 + k0 + lc];
        __syncthreads();
        As[lc + 0][lr] = a0.x; As[lc + 1][lr] = a0.y; As[lc + 2][lr] = a0.z; As[lc + 3][lr] = a0.w;
        As[lc + 0][lr + 64] = a1.x; As[lc + 1][lr + 64] = a1.y; As[lc + 2][lr + 64] = a1.z; As[lc + 3][lr + 64] = a1.w;
        Bs[lc + 0][lr] = b0.x; Bs[lc + 1][lr] = b0.y; Bs[lc + 2][lr] = b0.z; Bs[lc + 3][lr] = b0.w;
        __syncthreads();
#pragma unroll
        for (int kk = 0; kk < 16; ++kk) {
            const float4 av0 = *(const float4*)&As[kk][ty * 8];
            const float4 av1 = *(const float4*)&As[kk][ty * 8 + 4];
            const float4 bv  = *(const float4*)&Bs[kk][tx * 4];
            const float ar[8] = {av0.x, av0.y, av0.z, av0.w, av1.x, av1.y, av1.z, av1.w};
            const float br[4] = {bv.x, bv.y, bv.z, bv.w};
#pragma unroll
            for (int i = 0; i < 8; ++i)
#pragma unroll
                for (int j = 0; j < 4; ++j)
                    acc[i][j] = fmaf(ar[i], br[j], acc[i][j]);
        }
    }

#pragma unroll
    for (int i = 0; i < 8; ++i) {
        const int m = m0 + ty * 8 + i;
#pragma unroll
        for (int j = 0; j < 4; ++j) {
            const int o = n0 + tx * 4 + j;
            out[(size_t)m * 256 + o] = acc[i][j] + pb[o];
        }
    }
}

// ---------------------------------------------------------------------------
extern "C" void kernel_launch(void* const* d_in, const int* in_sizes, int n_in,
                              void* d_out, int out_size)
{
    const float* x          = (const float*)d_in[0];
    const float* mask       = (const float*)d_in[1];
    const float* qkv_w      = (const float*)d_in[2];
    const float* q_bias     = (const float*)d_in[3];
    const float* v_bias     = (const float*)d_in[4];
    const float* logit_sc   = (const float*)d_in[5];
    const float* cpb_w1     = (const float*)d_in[6];
    const float* cpb_b1     = (const float*)d_in[7];
    const float* cpb_w2     = (const float*)d_in[8];
    const float* proj_w     = (const float*)d_in[9];
    const float* proj_b     = (const float*)d_in[10];
    const float* table      = (const float*)d_in[11];
    const int*   rel_idx    = (const int*)d_in[12];

    const int B  = in_sizes[0] / (NTOK * CDIM);      // 2048
    const int nW = in_sizes[1] / NN2;                // 64
    const int M  = B * NTOK;                         // 100352

    cpb_kernel<<<1, 256>>>(table, cpb_w1, cpb_b1, cpb_w2, rel_idx);
    sgemm_qkv<<<dim3(768 / 64, M / 128), 256>>>(x, qkv_w, q_bias, v_bias);
    attn_kernel<<<dim3(B, HEADS), 128>>>(mask, logit_sc, nW);
    sgemm_proj<<<dim3(256 / 64, M / 128), 256>>>(proj_w, proj_b, (float*)d_out);
}

// round 2
// speedup vs baseline: 1.5444x; 1.5444x over previous
#include <cuda_runtime.h>
#include <math.h>

#define NTOK   49
#define CDIM   256
#define HEADS  8
#define HD     32
#define BMAX   2048
#define NN2    2401   // 49*49

// Scratch (allocation-free: __device__ globals)
__device__ float g_qkv[BMAX * 3 * HEADS * NTOK * HD];   // [B][3][H][49][32]
__device__ float g_att[BMAX * NTOK * CDIM];             // [B*49][256]
__device__ float g_bias[HEADS * NN2];                   // 16*sigmoid(cpb)

__device__ __forceinline__ float to_tf32(float x) {
    unsigned u;
    asm("cvt.rna.tf32.f32 %0, %1;" : "=r"(u) : "f"(x));
    return __uint_as_float(u);
}

__device__ __forceinline__ void mma_tf32(float* c, const unsigned* a, const unsigned* b) {
    asm volatile(
        "mma.sync.aligned.m16n8k8.row.col.f32.tf32.tf32.f32 "
        "{%0,%1,%2,%3}, {%4,%5,%6,%7}, {%8,%9}, {%0,%1,%2,%3};"
        : "+f"(c[0]), "+f"(c[1]), "+f"(c[2]), "+f"(c[3])
        : "r"(a[0]), "r"(a[1]), "r"(a[2]), "r"(a[3]), "r"(b[0]), "r"(b[1]));
}

// ---------------------------------------------------------------------------
// CPB MLP (tiny, one block)
// ---------------------------------------------------------------------------
__global__ void cpb_kernel(const float* __restrict__ table,
                           const float* __restrict__ w1,
                           const float* __restrict__ b1,
                           const float* __restrict__ w2,
                           const int*   __restrict__ idx)
{
    __shared__ float t8[169][8];
    const int tid = threadIdx.x;
    for (int e = tid; e < 169 * 8; e += blockDim.x) {
        const int r = e >> 3, hh = e & 7;
        const float t0 = table[r * 2 + 0];
        const float t1 = table[r * 2 + 1];
        float s = 0.f;
        for (int j = 0; j < 512; ++j) {
            float hv = fmaf(t0, w1[j * 2 + 0], fmaf(t1, w1[j * 2 + 1], b1[j]));
            hv = fmaxf(hv, 0.f);
            s = fmaf(hv, w2[hh * 512 + j], s);
        }
        t8[r][hh] = s;
    }
    __syncthreads();
    for (int e = tid; e < HEADS * NN2; e += blockDim.x) {
        const int h = e / NN2, ij = e % NN2;
        const float bv = t8[idx[ij]][h];
        g_bias[e] = 16.f / (1.f + __expf(-bv));
    }
}

// ---------------------------------------------------------------------------
// tf32 tensor-core GEMM core. BM=128, BN=64, BK=32, 8 warps (4x2),
// warp tile 32x32 as 2(m) x 4(n) m16n8k8 fragments, 4 k-steps per BK.
// As[m][k] pad 36, Bs[n][k] pad 36 -> conflict-free fragment LDS.
// Accumulators handed back to caller-specific epilogue via macro body.
// ---------------------------------------------------------------------------
#define GEMM_CORE(XPTR, WPTR)                                                     \
    __shared__ float As[128][36];                                                 \
    __shared__ float Bs[64][36];                                                  \
    const int tid = threadIdx.x;                                                  \
    const int lane = tid & 31, wid = tid >> 5;                                    \
    const int wm = (wid & 3) * 32;   /* warp m offset in block */                 \
    const int wn = (wid >> 2) * 32;  /* warp n offset in block */                 \
    const int g = lane >> 2, tg = lane & 3;                                       \
    const int m0 = blockIdx.y * 128;                                              \
    const int n0 = blockIdx.x * 64;                                               \
    const int ra = tid >> 3, ca = (tid & 7) * 4;   /* A loader: 32 rows/pass */   \
    const int rb = tid >> 2, cb = (tid & 3) * 8;   /* B loader: 64 rows */        \
    float acc[2][4][4];                                                           \
    _Pragma("unroll") for (int i = 0; i < 2; ++i)                                 \
    _Pragma("unroll") for (int j = 0; j < 4; ++j)                                 \
    _Pragma("unroll") for (int r = 0; r < 4; ++r) acc[i][j][r] = 0.f;             \
    for (int kb = 0; kb < 8; ++kb) {                                              \
        const int k0 = kb * 32;                                                   \
        float4 av[4], bv[2];                                                      \
        _Pragma("unroll") for (int p = 0; p < 4; ++p)                             \
            av[p] = *(const float4*)&(XPTR)[(size_t)(m0 + p * 32 + ra) * 256 + k0 + ca]; \
        bv[0] = *(const float4*)&(WPTR)[(size_t)(n0 + rb) * 256 + k0 + cb];       \
        bv[1] = *(const float4*)&(WPTR)[(size_t)(n0 + rb) * 256 + k0 + cb + 4];   \
        __syncthreads();                                                          \
        _Pragma("unroll") for (int p = 0; p < 4; ++p) {                           \
            float* d = &As[p * 32 + ra][ca];                                      \
            d[0] = to_tf32(av[p].x); d[1] = to_tf32(av[p].y);                     \
            d[2] = to_tf32(av[p].z); d[3] = to_tf32(av[p].w);                     \
        }                                                                         \
        {                                                                         \
            float* d = &Bs[rb][cb];                                               \
            d[0] = to_tf32(bv[0].x); d[1] = to_tf32(bv[0].y);                     \
            d[2] = to_tf32(bv[0].z); d[3] = to_tf32(bv[0].w);                     \
            d[4] = to_tf32(bv[1].x); d[5] = to_tf32(bv[1].y);                     \
            d[6] = to_tf32(bv[1].z); d[7] = to_tf32(bv[1].w);                     \
        }                                                                         \
        __syncthreads();                                                          \
        _Pragma("unroll") for (int ks = 0; ks < 4; ++ks) {                        \
            const int kk = ks * 8;                                                \
            unsigned af[2][4], bf[4][2];                                          \
            _Pragma("unroll") for (int mi = 0; mi < 2; ++mi) {                    \
                const int r = wm + mi * 16 + g;                                   \
                af[mi][0] = __float_as_uint(As[r    ][kk + tg]);                  \
                af[mi][1] = __float_as_uint(As[r + 8][kk + tg]);                  \
                af[mi][2] = __float_as_uint(As[r    ][kk + tg + 4]);              \
                af[mi][3] = __float_as_uint(As[r + 8][kk + tg + 4]);              \
            }                                                                     \
            _Pragma("unroll") for (int ni = 0; ni < 4; ++ni) {                    \
                const int c = wn + ni * 8 + g;                                    \
                bf[ni][0] = __float_as_uint(Bs[c][kk + tg]);                      \
                bf[ni][1] = __float_as_uint(Bs[c][kk + tg + 4]);                  \
            }                                                                     \
            _Pragma("unroll") for (int mi = 0; mi < 2; ++mi)                      \
            _Pragma("unroll") for (int ni = 0; ni < 4; ++ni)                      \
                mma_tf32(acc[mi][ni], af[mi], bf[ni]);                            \
        }                                                                         \
    }

// ---------------------------------------------------------------------------
// QKV GEMM: Y[M,768] = X @ qkv_w^T + bias, scattered into g_qkv layout
// ---------------------------------------------------------------------------
__global__ __launch_bounds__(256) void mma_qkv(const float* __restrict__ X,
                                               const float* __restrict__ W,
                                               const float* __restrict__ qb,
                                               const float* __restrict__ vb)
{
    GEMM_CORE(X, W)

    const int which = n0 >> 8;   // 64-wide block lies inside one 256 chunk
#pragma unroll
    for (int mi = 0; mi < 2; ++mi) {
        const int mA = m0 + wm + mi * 16 + g;
        const int mB = mA + 8;
        const int bbA = mA / NTOK, nnA = mA % NTOK;
        const int bbB = mB / NTOK, nnB = mB % NTOK;
#pragma unroll
        for (int ni = 0; ni < 4; ++ni) {
#pragma unroll
            for (int cc = 0; cc < 2; ++cc) {
                const int o = n0 + wn + ni * 8 + tg * 2 + cc;
                const int rem = o & 255;
                const float bias = (which == 0) ? qb[rem] : ((which == 2) ? vb[rem] : 0.f);
                const int h = rem >> 5, d = rem & 31;
                g_qkv[((size_t)((bbA * 3 + which) * HEADS + h)) * (NTOK * HD) + nnA * HD + d] =
                    acc[mi][ni][cc] + bias;
                g_qkv[((size_t)((bbB * 3 + which) * HEADS + h)) * (NTOK * HD) + nnB * HD + d] =
                    acc[mi][ni][2 + cc] + bias;
            }
        }
    }
}

// ---------------------------------------------------------------------------
// Proj GEMM: out[M,256] = g_att @ proj_w^T + proj_b
// ---------------------------------------------------------------------------
__global__ __launch_bounds__(256) void mma_proj(const float* __restrict__ W,
                                                const float* __restrict__ pb,
                                                float* __restrict__ out)
{
    GEMM_CORE(g_att, W)

#pragma unroll
    for (int mi = 0; mi < 2; ++mi) {
        const int mA = m0 + wm + mi * 16 + g;
#pragma unroll
        for (int ni = 0; ni < 4; ++ni) {
#pragma unroll
            for (int cc = 0; cc < 2; ++cc) {
                const int o = n0 + wn + ni * 8 + tg * 2 + cc;
                const float bias = pb[o];
                out[(size_t)mA * 256 + o]       = acc[mi][ni][cc]     + bias;
                out[(size_t)(mA + 8) * 256 + o] = acc[mi][ni][2 + cc] + bias;
            }
        }
    }
}

// ---------------------------------------------------------------------------
// Attention: one block per (b, h). 128 threads (4 warps), lane == head-dim.
// ---------------------------------------------------------------------------
__global__ __launch_bounds__(128) void attn_kernel(const float* __restrict__ mask,
                                                   const float* __restrict__ logit_scale,
                                                   int nW)
{
    __shared__ float qn[NTOK][33];
    __shared__ float kn[NTOK][33];
    __shared__ float vs[NTOK][33];
    __shared__ float at[NTOK][56];

    const int b = blockIdx.x, h = blockIdx.y;
    const int tid = threadIdx.x, w = tid >> 5, lane = tid & 31;
    const float scale = __expf(fminf(logit_scale[h], 4.605170185988092f)); // ln(100)

    const float* qptr = &g_qkv[((size_t)((b * 3 + 0) * HEADS + h)) * (NTOK * HD)];
    const float* kptr = &g_qkv[((size_t)((b * 3 + 1) * HEADS + h)) * (NTOK * HD)];
    const float* vptr = &g_qkv[((size_t)((b * 3 + 2) * HEADS + h)) * (NTOK * HD)];

    for (int r = w; r < NTOK; r += 4) {
        const float qv = qptr[r * HD + lane];
        const float kv = kptr[r * HD + lane];
        float sq = qv * qv, sk = kv * kv;
#pragma unroll
        for (int o = 16; o > 0; o >>= 1) {
            sq += __shfl_xor_sync(0xffffffffu, sq, o);
            sk += __shfl_xor_sync(0xffffffffu, sk, o);
        }
        qn[r][lane] = qv * (scale / fmaxf(sqrtf(sq), 1e-12f));
        kn[r][lane] = kv / fmaxf(sqrtf(sk), 1e-12f);
        vs[r][lane] = vptr[r * HD + lane];
    }
    __syncthreads();

    const int j2 = lane + 32;
    const int j2c = (j2 < NTOK) ? j2 : NTOK - 1;
    const float* bptr = &g_bias[h * NN2];
    const float* mptr = &mask[(size_t)(b % nW) * NN2];

    for (int r = w; r < NTOK; r += 4) {
        float a0 = 0.f, a1 = 0.f;
#pragma unroll
        for (int d = 0; d < HD; ++d) {
            const float qd = qn[r][d];
            a0 = fmaf(qd, kn[lane][d], a0);
            a1 = fmaf(qd, kn[j2c][d], a1);
        }
        at[r][lane] = a0 + bptr[r * NTOK + lane] + mptr[r * NTOK + lane];
        if (j2 < NTOK) at[r][j2] = a1 + bptr[r * NTOK + j2] + mptr[r * NTOK + j2];
    }
    __syncthreads();

    for (int r = w; r < NTOK; r += 4) {
        const float a0 = at[r][lane];
        const float a1 = (j2 < NTOK) ? at[r][j2] : -1e30f;
        float mx = fmaxf(a0, a1);
#pragma unroll
        for (int o = 16; o > 0; o >>= 1) mx = fmaxf(mx, __shfl_xor_sync(0xffffffffu, mx, o));
        const float e0 = __expf(a0 - mx);
        const float e1 = (j2 < NTOK) ? __expf(a1 - mx) : 0.f;
        float s = e0 + e1;
#pragma unroll
        for (int o = 16; o > 0; o >>= 1) s += __shfl_xor_sync(0xffffffffu, s, o);
        const float inv = 1.f / s;
        at[r][lane] = e0 * inv;
        if (j2 < NTOK) at[r][j2] = e1 * inv;
    }
    __syncthreads();

    for (int r = w; r < NTOK; r += 4) {
        float acc = 0.f;
#pragma unroll
        for (int j = 0; j < NTOK; ++j) acc = fmaf(at[r][j], vs[j][lane], acc);
        g_att[((size_t)(b * NTOK + r)) * CDIM + h * HD + lane] = acc;
    }
}

// ---------------------------------------------------------------------------
extern "C" void kernel_launch(void* const* d_in, const int* in_sizes, int n_in,
                              void* d_out, int out_size)
{
    const float* x        = (const float*)d_in[0];
    const float* mask     = (const float*)d_in[1];
    const float* qkv_w    = (const float*)d_in[2];
    const float* q_bias   = (const float*)d_in[3];
    const float* v_bias   = (const float*)d_in[4];
    const float* logit_sc = (const float*)d_in[5];
    const float* cpb_w1   = (const float*)d_in[6];
    const float* cpb_b1   = (const float*)d_in[7];
    const float* cpb_w2   = (const float*)d_in[8];
    const float* proj_w   = (const float*)d_in[9];
    const float* proj_b   = (const float*)d_in[10];
    const float* table    = (const float*)d_in[11];
    const int*   rel_idx  = (const int*)d_in[12];

    const int B  = in_sizes[0] / (NTOK * CDIM);      // 2048
    const int nW = in_sizes[1] / NN2;                // 64
    const int M  = B * NTOK;                         // 100352

    cpb_kernel<<<1, 256>>>(table, cpb_w1, cpb_b1, cpb_w2, rel_idx);
    mma_qkv<<<dim3(768 / 64, M / 128), 256>>>(x, qkv_w, q_bias, v_bias);
    attn_kernel<<<dim3(B, HEADS), 128>>>(mask, logit_sc, nW);
    mma_proj<<<dim3(256 / 64, M / 128), 256>>>(proj_w, proj_b, (float*)d_out);
}

// round 3
// speedup vs baseline: 1.8201x; 1.1786x over previous
#include <cuda_runtime.h>
#include <math.h>

#define NTOK   49
#define CDIM   256
#define HEADS  8
#define HD     32
#define BMAX   2048
#define NN2    2401   // 49*49

// Scratch (allocation-free: __device__ globals)
__device__ float g_qkv[BMAX * NTOK * 768];   // [M][768]  (q|k|v per row)
__device__ float g_att[BMAX * NTOK * CDIM];  // [M][256]
__device__ float g_bias[HEADS * NN2];        // 16*sigmoid(cpb)

__device__ __forceinline__ unsigned ldtf(const float* p) {
    unsigned u;
    asm("cvt.rna.tf32.f32 %0, %1;" : "=r"(u) : "f"(*p));
    return u;
}

__device__ __forceinline__ void mma_tf32(float* c, const unsigned* a, const unsigned* b) {
    asm volatile(
        "mma.sync.aligned.m16n8k8.row.col.f32.tf32.tf32.f32 "
        "{%0,%1,%2,%3}, {%4,%5,%6,%7}, {%8,%9}, {%0,%1,%2,%3};"
        : "+f"(c[0]), "+f"(c[1]), "+f"(c[2]), "+f"(c[3])
        : "r"(a[0]), "r"(a[1]), "r"(a[2]), "r"(a[3]), "r"(b[0]), "r"(b[1]));
}

#define CPA16(dst_u32, src_ptr) \
    asm volatile("cp.async.cg.shared.global [%0], [%1], 16;" :: "r"(dst_u32), "l"(src_ptr))

// ---------------------------------------------------------------------------
// CPB MLP (tiny, one block)
// ---------------------------------------------------------------------------
__global__ void cpb_kernel(const float* __restrict__ table,
                           const float* __restrict__ w1,
                           const float* __restrict__ b1,
                           const float* __restrict__ w2,
                           const int*   __restrict__ idx)
{
    __shared__ float t8[169][8];
    const int tid = threadIdx.x;
    for (int e = tid; e < 169 * 8; e += blockDim.x) {
        const int r = e >> 3, hh = e & 7;
        const float t0 = table[r * 2 + 0];
        const float t1 = table[r * 2 + 1];
        float s = 0.f;
        for (int j = 0; j < 512; ++j) {
            float hv = fmaf(t0, w1[j * 2 + 0], fmaf(t1, w1[j * 2 + 1], b1[j]));
            hv = fmaxf(hv, 0.f);
            s = fmaf(hv, w2[hh * 512 + j], s);
        }
        t8[r][hh] = s;
    }
    __syncthreads();
    for (int e = tid; e < HEADS * NN2; e += blockDim.x) {
        const int h = e / NN2, ij = e % NN2;
        const float bv = t8[idx[ij]][h];
        g_bias[e] = 16.f / (1.f + __expf(-bv));
    }
}

// ---------------------------------------------------------------------------
// cp.async double-buffered tf32 GEMM core.
// BM=128, BN=128, BK=16, 2 stages, 256 threads.
// Warp grid 2(m) x 4(n); warp tile 64x32: 4 m-frags x 4 n-frags of m16n8k8.
// smem rows padded to 20 floats (80B, 16B-aligned, conflict-free frag LDS).
// ---------------------------------------------------------------------------
#define GEMM_PIPE(XPTR, WPTR)                                                     \
    __shared__ float As[2][128][20];                                              \
    __shared__ float Bs[2][128][20];                                              \
    const int tid = threadIdx.x;                                                  \
    const int lane = tid & 31, wid = tid >> 5;                                    \
    const int g = lane >> 2, tg = lane & 3;                                       \
    const int wm = (wid & 1) * 64, wn = (wid >> 1) * 32;                          \
    const int m0 = blockIdx.y * 128, n0 = blockIdx.x * 128;                       \
    const int lrow = tid >> 2, lcol = (tid & 3) * 4;                              \
    const float* gA0 = (XPTR) + (size_t)(m0 + lrow) * 256 + lcol;                 \
    const float* gA1 = gA0 + (size_t)64 * 256;                                    \
    const float* gB0 = (WPTR) + (size_t)(n0 + lrow) * 256 + lcol;                 \
    const float* gB1 = gB0 + (size_t)64 * 256;                                    \
    const unsigned sA = (unsigned)__cvta_generic_to_shared(&As[0][lrow][lcol]);   \
    const unsigned sB = (unsigned)__cvta_generic_to_shared(&Bs[0][lrow][lcol]);   \
    const unsigned STG = 128 * 20 * 4;   /* stage stride bytes */                 \
    const unsigned HLF = 64 * 20 * 4;    /* 64-row offset */                      \
    float acc[4][4][4];                                                           \
    _Pragma("unroll") for (int i = 0; i < 4; ++i)                                 \
    _Pragma("unroll") for (int j = 0; j < 4; ++j)                                 \
    _Pragma("unroll") for (int r = 0; r < 4; ++r) acc[i][j][r] = 0.f;             \
    CPA16(sA,             gA0);                                                   \
    CPA16(sA + HLF,       gA1);                                                   \
    CPA16(sB,             gB0);                                                   \
    CPA16(sB + HLF,       gB1);                                                   \
    asm volatile("cp.async.commit_group;");                                       \
    for (int kb = 0; kb < 16; ++kb) {                                             \
        if (kb < 15) {                                                            \
            const int sNext = (kb + 1) & 1;                                       \
            const int kOff = (kb + 1) * 16;                                       \
            CPA16(sA + sNext * STG,       gA0 + kOff);                            \
            CPA16(sA + sNext * STG + HLF, gA1 + kOff);                            \
            CPA16(sB + sNext * STG,       gB0 + kOff);                            \
            CPA16(sB + sNext * STG + HLF, gB1 + kOff);                            \
            asm volatile("cp.async.commit_group;");                               \
            asm volatile("cp.async.wait_group 1;");                               \
        } else {                                                                  \
            asm volatile("cp.async.wait_group 0;");                               \
        }                                                                         \
        __syncthreads();                                                          \
        const int s = kb & 1;                                                     \
        _Pragma("unroll") for (int ks = 0; ks < 2; ++ks) {                        \
            const int kk = ks * 8;                                                \
            unsigned af[4][4], bf[4][2];                                          \
            _Pragma("unroll") for (int mi = 0; mi < 4; ++mi) {                    \
                const int r = wm + mi * 16 + g;                                   \
                af[mi][0] = ldtf(&As[s][r    ][kk + tg]);                         \
                af[mi][1] = ldtf(&As[s][r + 8][kk + tg]);                         \
                af[mi][2] = ldtf(&As[s][r    ][kk + tg + 4]);                     \
                af[mi][3] = ldtf(&As[s][r + 8][kk + tg + 4]);                     \
            }                                                                     \
            _Pragma("unroll") for (int ni = 0; ni < 4; ++ni) {                    \
                const int c = wn + ni * 8 + g;                                    \
                bf[ni][0] = ldtf(&Bs[s][c][kk + tg]);                             \
                bf[ni][1] = ldtf(&Bs[s][c][kk + tg + 4]);                         \
            }                                                                     \
            _Pragma("unroll") for (int mi = 0; mi < 4; ++mi)                      \
            _Pragma("unroll") for (int ni = 0; ni < 4; ++ni)                      \
                mma_tf32(acc[mi][ni], af[mi], bf[ni]);                            \
        }                                                                         \
        __syncthreads();                                                          \
    }

// ---------------------------------------------------------------------------
// QKV GEMM: g_qkv[M,768] = X @ qkv_w^T + qkv_bias   (coalesced epilogue)
// ---------------------------------------------------------------------------
__device__ __forceinline__ float qkvb(int o, const float* qb, const float* vb) {
    return (o < 256) ? qb[o] : ((o < 512) ? 0.f : vb[o - 512]);
}

__global__ __launch_bounds__(256) void mma_qkv(const float* __restrict__ X,
                                               const float* __restrict__ W,
                                               const float* __restrict__ qb,
                                               const float* __restrict__ vb)
{
    GEMM_PIPE(X, W)

#pragma unroll
    for (int mi = 0; mi < 4; ++mi) {
        const int mA = m0 + wm + mi * 16 + g;
#pragma unroll
        for (int ni = 0; ni < 4; ++ni) {
            const int o = n0 + wn + ni * 8 + tg * 2;
            const float b0 = qkvb(o, qb, vb), b1 = qkvb(o + 1, qb, vb);
            float2 v0 = make_float2(acc[mi][ni][0] + b0, acc[mi][ni][1] + b1);
            float2 v1 = make_float2(acc[mi][ni][2] + b0, acc[mi][ni][3] + b1);
            *(float2*)&g_qkv[(size_t)mA * 768 + o]       = v0;
            *(float2*)&g_qkv[(size_t)(mA + 8) * 768 + o] = v1;
        }
    }
}

// ---------------------------------------------------------------------------
// Proj GEMM: out[M,256] = g_att @ proj_w^T + proj_b
// ---------------------------------------------------------------------------
__global__ __launch_bounds__(256) void mma_proj(const float* __restrict__ W,
                                                const float* __restrict__ pb,
                                                float* __restrict__ out)
{
    GEMM_PIPE(g_att, W)

#pragma unroll
    for (int mi = 0; mi < 4; ++mi) {
        const int mA = m0 + wm + mi * 16 + g;
#pragma unroll
        for (int ni = 0; ni < 4; ++ni) {
            const int o = n0 + wn + ni * 8 + tg * 2;
            const float b0 = pb[o], b1 = pb[o + 1];
            float2 v0 = make_float2(acc[mi][ni][0] + b0, acc[mi][ni][1] + b1);
            float2 v1 = make_float2(acc[mi][ni][2] + b0, acc[mi][ni][3] + b1);
            *(float2*)&out[(size_t)mA * 256 + o]       = v0;
            *(float2*)&out[(size_t)(mA + 8) * 256 + o] = v1;
        }
    }
}

// ---------------------------------------------------------------------------
// Attention: one block per (b, h). 128 threads (4 warps), lane == head-dim.
// float4-vectorized shared-memory inner loops.
// ---------------------------------------------------------------------------
__global__ __launch_bounds__(128) void attn_kernel(const float* __restrict__ mask,
                                                   const float* __restrict__ logit_scale,
                                                   int nW)
{
    __shared__ float qn[NTOK][36];
    __shared__ float kn[NTOK][36];
    __shared__ float vt[32][52];     // transposed V: [d][token]
    __shared__ float at[NTOK][56];

    const int b = blockIdx.x, h = blockIdx.y;
    const int tid = threadIdx.x, w = tid >> 5, lane = tid & 31;
    const float scale = __expf(fminf(logit_scale[h], 4.605170185988092f)); // ln(100)

    // q/k/v gathered from [M,768] layout: row (b*49+r), cols h*32+lane (+0/256/512)
    const float* base = &g_qkv[(size_t)(b * NTOK) * 768 + h * HD];

    for (int r = w; r < NTOK; r += 4) {
        const float* rp = base + (size_t)r * 768;
        const float qv = rp[lane];
        const float kv = rp[256 + lane];
        const float vv = rp[512 + lane];
        float sq = qv * qv, sk = kv * kv;
#pragma unroll
        for (int o = 16; o > 0; o >>= 1) {
            sq += __shfl_xor_sync(0xffffffffu, sq, o);
            sk += __shfl_xor_sync(0xffffffffu, sk, o);
        }
        qn[r][lane] = qv * (scale / fmaxf(sqrtf(sq), 1e-12f));
        kn[r][lane] = kv / fmaxf(sqrtf(sk), 1e-12f);
        vt[lane][r] = vv;
    }
    __syncthreads();

    const int j2 = lane + 32;
    const int j2c = (j2 < NTOK) ? j2 : NTOK - 1;
    const float* bptr = &g_bias[h * NN2];
    const float* mptr = &mask[(size_t)(b % nW) * NN2];

    // QK^T + bias + mask  (float4 over head-dim)
    for (int r = w; r < NTOK; r += 4) {
        float a0 = 0.f, a1 = 0.f;
#pragma unroll
        for (int d4 = 0; d4 < 8; ++d4) {
            const float4 q4 = *(const float4*)&qn[r][d4 * 4];
            const float4 ka = *(const float4*)&kn[lane][d4 * 4];
            const float4 kb = *(const float4*)&kn[j2c][d4 * 4];
            a0 = fmaf(q4.x, ka.x, a0); a0 = fmaf(q4.y, ka.y, a0);
            a0 = fmaf(q4.z, ka.z, a0); a0 = fmaf(q4.w, ka.w, a0);
            a1 = fmaf(q4.x, kb.x, a1); a1 = fmaf(q4.y, kb.y, a1);
            a1 = fmaf(q4.z, kb.z, a1); a1 = fmaf(q4.w, kb.w, a1);
        }
        at[r][lane] = a0 + bptr[r * NTOK + lane] + mptr[r * NTOK + lane];
        if (j2 < NTOK) at[r][j2] = a1 + bptr[r * NTOK + j2] + mptr[r * NTOK + j2];
    }
    __syncthreads();

    // row softmax
    for (int r = w; r < NTOK; r += 4) {
        const float a0 = at[r][lane];
        const float a1 = (j2 < NTOK) ? at[r][j2] : -1e30f;
        float mx = fmaxf(a0, a1);
#pragma unroll
        for (int o = 16; o > 0; o >>= 1) mx = fmaxf(mx, __shfl_xor_sync(0xffffffffu, mx, o));
        const float e0 = __expf(a0 - mx);
        const float e1 = (j2 < NTOK) ? __expf(a1 - mx) : 0.f;
        float s = e0 + e1;
#pragma unroll
        for (int o = 16; o > 0; o >>= 1) s += __shfl_xor_sync(0xffffffffu, s, o);
        const float inv = 1.f / s;
        at[r][lane] = e0 * inv;
        if (j2 < NTOK) at[r][j2] = e1 * inv;
    }
    __syncthreads();

    // attn @ V  (float4 over tokens, transposed V)
    for (int r = w; r < NTOK; r += 4) {
        float acc = 0.f;
#pragma unroll
        for (int j4 = 0; j4 < 12; ++j4) {
            const float4 a4 = *(const float4*)&at[r][j4 * 4];
            const float4 v4 = *(const float4*)&vt[lane][j4 * 4];
            acc = fmaf(a4.x, v4.x, acc); acc = fmaf(a4.y, v4.y, acc);
            acc = fmaf(a4.z, v4.z, acc); acc = fmaf(a4.w, v4.w, acc);
        }
        acc = fmaf(at[r][48], vt[lane][48], acc);
        g_att[(size_t)(b * NTOK + r) * CDIM + h * HD + lane] = acc;
    }
}

// ---------------------------------------------------------------------------
extern "C" void kernel_launch(void* const* d_in, const int* in_sizes, int n_in,
                              void* d_out, int out_size)
{
    const float* x        = (const float*)d_in[0];
    const float* mask     = (const float*)d_in[1];
    const float* qkv_w    = (const float*)d_in[2];
    const float* q_bias   = (const float*)d_in[3];
    const float* v_bias   = (const float*)d_in[4];
    const float* logit_sc = (const float*)d_in[5];
    const float* cpb_w1   = (const float*)d_in[6];
    const float* cpb_b1   = (const float*)d_in[7];
    const float* cpb_w2   = (const float*)d_in[8];
    const float* proj_w   = (const float*)d_in[9];
    const float* proj_b   = (const float*)d_in[10];
    const float* table    = (const float*)d_in[11];
    const int*   rel_idx  = (const int*)d_in[12];

    const int B  = in_sizes[0] / (NTOK * CDIM);      // 2048
    const int nW = in_sizes[1] / NN2;                // 64
    const int M  = B * NTOK;                         // 100352

    mma_qkv<<<dim3(768 / 128, M / 128), 256>>>(x, qkv_w, q_bias, v_bias);
    cpb_kernel<<<1, 256>>>(table, cpb_w1, cpb_b1, cpb_w2, rel_idx);
    attn_kernel<<<dim3(B, HEADS), 128>>>(mask, logit_sc, nW);
    mma_proj<<<dim3(256 / 128, M / 128), 256>>>(proj_w, proj_b, (float*)d_out);
}